// round 14
// baseline (speedup 1.0000x reference)
#include <cuda_runtime.h>
#include <cuda_bf16.h>
#include <cstdint>

#define B   8
#define C   64
#define IC  32
#define HW  65536
#define NV  32768
#define TOT (IC*HW)

// ---------------- scratch ----------------
__device__ float s_theta[(size_t)B*TOT];
__device__ float s_att[B*64*64];
__device__ float s_sum[2*B];               // [0..7]=Sphi, [8..15]=Sg
__device__ uint32_t s_CH[8*128*36];        // C bf16-hi image, row=hi*64+o, pitch 36 words
__device__ uint32_t s_CL[8*128*36];        // C bf16-lo image

// ---------------- helpers ----------------
__device__ __forceinline__ uint32_t smem_u32(const void* p) {
    uint32_t a;
    asm("{ .reg .u64 t; cvta.to.shared.u64 t, %1; cvt.u32.u64 %0, t; }" : "=r"(a) : "l"(p));
    return a;
}
__device__ __forceinline__ void ldsm_x4(uint32_t& r0, uint32_t& r1, uint32_t& r2, uint32_t& r3, uint32_t addr) {
    asm volatile("ldmatrix.sync.aligned.m8n8.x4.shared.b16 {%0,%1,%2,%3}, [%4];"
                 : "=r"(r0), "=r"(r1), "=r"(r2), "=r"(r3) : "r"(addr));
}
__device__ __forceinline__ void mma16816(float* c, uint32_t a0, uint32_t a1, uint32_t a2, uint32_t a3,
                                         uint32_t b0, uint32_t b1) {
    asm volatile("mma.sync.aligned.m16n8k16.row.col.f32.bf16.bf16.f32 "
                 "{%0,%1,%2,%3}, {%4,%5,%6,%7}, {%8,%9}, {%0,%1,%2,%3};"
                 : "+f"(c[0]), "+f"(c[1]), "+f"(c[2]), "+f"(c[3])
                 : "r"(a0), "r"(a1), "r"(a2), "r"(a3), "r"(b0), "r"(b1));
}
__device__ __forceinline__ void split_pair(float v0, float v1, uint32_t& hpk, uint32_t& lpk) {
    __nv_bfloat16 h0 = __float2bfloat16_rn(v0), h1 = __float2bfloat16_rn(v1);
    hpk = (uint32_t)__bfloat16_as_ushort(h0) | ((uint32_t)__bfloat16_as_ushort(h1) << 16);
    float l0 = v0 - __bfloat162float(h0), l1 = v1 - __bfloat162float(h1);
    __nv_bfloat16 g0 = __float2bfloat16_rn(l0), g1 = __float2bfloat16_rn(l1);
    lpk = (uint32_t)__bfloat16_as_ushort(g0) | ((uint32_t)__bfloat16_as_ushort(g1) << 16);
}

#define PITCH  72
#define PITCHB 144

// smem offsets for k_fused (bytes)
#define OFF_AH 0
#define OFF_AL (128*PITCHB)
#define OFF_WH (2*128*PITCHB)
#define OFF_WL (2*128*PITCHB + 96*PITCHB)
#define OFF_EG (2*128*PITCHB + 2*96*PITCHB)
#define OFF_EP (OFF_EG + 64*PITCHB)
#define SMEM_FUSED (OFF_EP + 64*PITCHB)     // 82944 B

// smem for k_out (M=64): AH/AL 64*144, CH/CL 128*144
#define O_AH 0
#define O_AL (64*PITCHB)
#define O_CH (2*64*PITCHB)
#define O_CL (2*64*PITCHB + 128*PITCHB)
#define SMEM_OUT (2*64*PITCHB + 2*128*PITCHB)   // 55296 B

// ---------------- K0: reset accumulators ----------------
__global__ void k_init() {
    int i = blockIdx.x * 256 + threadIdx.x;
    if (i < B*4096) s_att[i] = 0.0f;
    if (i < 2*B) s_sum[i] = 0.0f;
}

// ---------------- K1: fused conv + exp + att-partial + theta store (R10 numerics) ----------------
// Conv loop: hh+hl for all tiles; lh (x-lo) for theta tiles only.
__global__ __launch_bounds__(256) void k_fused(const float* __restrict__ x,
                                               const float* __restrict__ wp,
                                               const float* __restrict__ wt,
                                               const float* __restrict__ wg) {
    extern __shared__ char dsm[];
    char* AH = dsm + OFF_AH;
    char* AL = dsm + OFF_AL;
    char* WH = dsm + OFF_WH;
    char* WL = dsm + OFF_WL;
    char* EG = dsm + OFF_EG;
    char* EP = dsm + OFF_EP;
    __shared__ float rsp[8], rsg[8];

    const int tid  = threadIdx.x;
    const int lane = tid & 31;
    const int wid  = tid >> 5;
    const int b    = blockIdx.x >> 7;
    const int v0   = (blockIdx.x & 127) << 8;

    // weights -> smem hi/lo: rows 0-31 phi, 32-63 g, 64-95 theta
    for (int i = tid; i < 96*32; i += 256) {
        int row = i >> 5, pr = i & 31;
        const float* src = (row < 32) ? (wp + row*64)
                          : (row < 64 ? wg + (row-32)*64 : wt + (row-64)*64);
        uint32_t h, l;
        split_pair(src[pr*2], src[pr*2+1], h, l);
        *(uint32_t*)(WH + row*PITCHB + pr*4) = h;
        *(uint32_t*)(WL + row*PITCHB + pr*4) = l;
    }

    const int mt = wid & 3;
    const int ng = wid >> 2;
    float attc[4][4];
    #pragma unroll
    for (int j = 0; j < 4; j++)
        #pragma unroll
        for (int q = 0; q < 4; q++) attc[j][q] = 0.0f;
    float sp = 0.0f, sg = 0.0f;

    const uint32_t arow  = (uint32_t)(wid*16 + (lane & 15)) * PITCHB + (uint32_t)(lane >> 4) * 16;
    const uint32_t boff  = (uint32_t)((lane >> 4)*8 + (lane & 7)) * PITCHB + (uint32_t)((lane >> 3) & 1) * 16;
    const uint32_t arow2 = (uint32_t)(mt*16 + (lane & 15)) * PITCHB + (uint32_t)(lane >> 4) * 16;
    const int qr = lane >> 2;
    const int qc = lane & 3;

    const uint32_t ahb = smem_u32(AH), alb = smem_u32(AL);
    const uint32_t whb = smem_u32(WH), wlb = smem_u32(WL);
    const uint32_t egb = smem_u32(EG), epb = smem_u32(EP);
    __syncthreads();

    for (int it = 0; it < 4; it++) {
        const int n0it = v0 + it*64;
        // ---- stage x tile: px 0-63 = half0, 64-127 = half1 ----
        {
            const int px = tid & 127;
            const int hi = px >> 6;
            const int j0 = (tid >> 7) * 16;
            const float* xb = x + ((size_t)b << 22) + (size_t)hi*NV + n0it + (px & 63);
            #pragma unroll
            for (int j = j0; j < j0 + 16; j++) {
                float v0f = xb[(size_t)(2*j)   << 16];
                float v1f = xb[(size_t)(2*j+1) << 16];
                uint32_t h, l;
                split_pair(v0f, v1f, h, l);
                *(uint32_t*)(AH + px*PITCHB + j*4) = h;
                *(uint32_t*)(AL + px*PITCHB + j*4) = l;
            }
        }
        __syncthreads();

        // ---- conv mma: hh+hl for all tiles; +lh for theta (pp 4,5) ----
        float c[12][4];
        #pragma unroll
        for (int nt = 0; nt < 12; nt++)
            #pragma unroll
            for (int q = 0; q < 4; q++) c[nt][q] = 0.0f;

        #pragma unroll
        for (int kk = 0; kk < 4; kk++) {
            uint32_t ah0, ah1, ah2, ah3, al0, al1, al2, al3;
            ldsm_x4(ah0, ah1, ah2, ah3, ahb + arow + kk*32);
            ldsm_x4(al0, al1, al2, al3, alb + arow + kk*32);
            #pragma unroll
            for (int pp = 0; pp < 6; pp++) {
                uint32_t bh0, bh1, bh2, bh3, bl0, bl1, bl2, bl3;
                ldsm_x4(bh0, bh1, bh2, bh3, whb + boff + (uint32_t)pp*16*PITCHB + kk*32);
                ldsm_x4(bl0, bl1, bl2, bl3, wlb + boff + (uint32_t)pp*16*PITCHB + kk*32);
                mma16816(c[2*pp],   ah0, ah1, ah2, ah3, bh0, bh1);
                mma16816(c[2*pp+1], ah0, ah1, ah2, ah3, bh2, bh3);
                mma16816(c[2*pp],   ah0, ah1, ah2, ah3, bl0, bl1);
                mma16816(c[2*pp+1], ah0, ah1, ah2, ah3, bl2, bl3);
                if (pp >= 4) {
                    mma16816(c[2*pp],   al0, al1, al2, al3, bh0, bh1);
                    mma16816(c[2*pp+1], al0, al1, al2, al3, bh2, bh3);
                }
            }
        }

        // ---- epilogue: theta -> gmem, exp(phi/g) -> smem bf16 ----
        const int r1 = wid*16 + qr;
        const int hi1 = r1 >> 6;
        const int nl1 = r1 & 63;
        #pragma unroll
        for (int nt = 0; nt < 12; nt++) {
            const int oc = nt*8 + qc*2;
            const int t  = oc >> 5;
            const int ocl = oc & 31;
            if (t == 2) {
                float* d0 = s_theta + (size_t)b*TOT + ((size_t)ocl << 16)
                          + (size_t)hi1*NV + n0it + nl1;
                d0[0] = c[nt][0];
                d0[1 << 16] = c[nt][1];
                d0[8] = c[nt][2];
                d0[(1 << 16) + 8] = c[nt][3];
            } else {
                char* base = (t == 1) ? EG : EP;
                float e0 = __expf(c[nt][0]);
                float e1 = __expf(c[nt][1]);
                float e2 = __expf(c[nt][2]);
                float e3 = __expf(c[nt][3]);
                *(__nv_bfloat16*)(base + (2*ocl + hi1)*PITCHB + nl1*2)         = __float2bfloat16_rn(e0);
                *(__nv_bfloat16*)(base + (2*ocl + 2 + hi1)*PITCHB + nl1*2)     = __float2bfloat16_rn(e1);
                *(__nv_bfloat16*)(base + (2*ocl + hi1)*PITCHB + (nl1+8)*2)     = __float2bfloat16_rn(e2);
                *(__nv_bfloat16*)(base + (2*ocl + 2 + hi1)*PITCHB + (nl1+8)*2) = __float2bfloat16_rn(e3);
                float s4 = (e0 + e1) + (e2 + e3);
                if (t == 0) sp += s4; else sg += s4;
            }
        }
        __syncthreads();

        // ---- att mma: attc += EG(m) @ EP(n)^T over k=64 local cols ----
        #pragma unroll
        for (int kk = 0; kk < 4; kk++) {
            uint32_t a0, a1, a2, a3;
            ldsm_x4(a0, a1, a2, a3, egb + arow2 + kk*32);
            #pragma unroll
            for (int p = 0; p < 2; p++) {
                uint32_t b0, b1, b2, b3;
                ldsm_x4(b0, b1, b2, b3, epb + boff + (uint32_t)(ng*4 + 2*p)*8*PITCHB + kk*32);
                mma16816(attc[2*p],   a0, a1, a2, a3, b0, b1);
                mma16816(attc[2*p+1], a0, a1, a2, a3, b2, b3);
            }
        }
        __syncthreads();
    }

    float* attb = s_att + b*4096;
    #pragma unroll
    for (int j = 0; j < 4; j++) {
        const int col = (ng*4 + j)*8 + qc*2;
        const int row = mt*16 + qr;
        atomicAdd(&attb[row*64 + col],           attc[j][0]);
        atomicAdd(&attb[row*64 + col + 1],       attc[j][1]);
        atomicAdd(&attb[(row + 8)*64 + col],     attc[j][2]);
        atomicAdd(&attb[(row + 8)*64 + col + 1], attc[j][3]);
    }

    #pragma unroll
    for (int off = 16; off; off >>= 1) {
        sp += __shfl_xor_sync(0xffffffffu, sp, off);
        sg += __shfl_xor_sync(0xffffffffu, sg, off);
    }
    if (lane == 0) { rsp[wid] = sp; rsg[wid] = sg; }
    __syncthreads();
    if (tid == 0) {
        float a = 0.0f, bm = 0.0f;
        #pragma unroll
        for (int i = 0; i < 8; i++) { a += rsp[i]; bm += rsg[i]; }
        atomicAdd(&s_sum[b],     a);
        atomicAdd(&s_sum[B + b], bm);
    }
}

// ---------------- K2: fold mask + norm into bf16 hi/lo C image (ldmatrix layout) ----------------
__global__ void k_cmat(const float* __restrict__ wm) {
    int idx = blockIdx.x * 256 + threadIdx.x;    // 32768
    int dd = idx & 31;
    int o  = (idx >> 5) & 63;
    int hi = (idx >> 11) & 1;
    int b  = idx >> 12;
    float inv = 1.0f / (s_sum[b] * s_sum[B + b]);
    const float* attb = s_att + b*4096;
    float a0 = 0.0f, a1 = 0.0f;
    #pragma unroll
    for (int i = 0; i < 32; i++) {
        float w = wm[o*32 + i];
        a0 += w * attb[(2*i + hi)*64 + 2*dd];
        a1 += w * attb[(2*i + hi)*64 + 2*dd + 1];
    }
    uint32_t h, l;
    split_pair(a0 * inv, a1 * inv, h, l);
    int word = b*4608 + (hi*64 + o)*36 + dd;
    s_CH[word] = h;
    s_CL[word] = l;
}

// ---------------- K3: Out = C @ theta, R8 3-pass loop, M=64 / 128-thread blocks ----------------
// Warp = one m16 tile x 16 n-tiles (same per-warp shape as R8); 4 blocks/SM.
__global__ __launch_bounds__(128) void k_out(float* __restrict__ out) {
    extern __shared__ char dsm[];
    char* AH = dsm + O_AH;
    char* AL = dsm + O_AL;
    char* CH = dsm + O_CH;
    char* CL = dsm + O_CL;

    const int tid  = threadIdx.x;
    const int lane = tid & 31;
    const int wid  = tid >> 5;
    const int b    = blockIdx.x >> 9;
    const int n0   = (blockIdx.x & 511) << 6;

    // stage C image: plain vector copy (pre-split in k_cmat)
    {
        const uint4* srcH = (const uint4*)(s_CH + b*4608);
        const uint4* srcL = (const uint4*)(s_CL + b*4608);
        uint4* dstH = (uint4*)CH;
        uint4* dstL = (uint4*)CL;
        #pragma unroll
        for (int i = 0; i < 9; i++) {
            int k = tid + i*128;
            if (k < 1152) { dstH[k] = srcH[k]; dstL[k] = srcL[k]; }
        }
    }
    // stage theta: A[n][d], d=2j,2j+1 from raw[j][(d&1)*NV + n]
    {
        const int px = tid & 63;
        const int j0 = (tid >> 6) * 16;
        const float* th = s_theta + (size_t)b*TOT + n0 + px;
        #pragma unroll
        for (int j = j0; j < j0 + 16; j++) {
            float v0 = th[(size_t)j << 16];
            float v1 = th[((size_t)j << 16) + NV];
            uint32_t h, l;
            split_pair(v0, v1, h, l);
            *(uint32_t*)(AH + px*PITCHB + j*4) = h;
            *(uint32_t*)(AL + px*PITCHB + j*4) = l;
        }
    }
    __syncthreads();

    const int m0 = wid * 16;
    float c[16][4];
    #pragma unroll
    for (int nt = 0; nt < 16; nt++)
        #pragma unroll
        for (int q = 0; q < 4; q++) c[nt][q] = 0.0f;

    const uint32_t arow = (uint32_t)(m0 + (lane & 15)) * PITCHB + (uint32_t)(lane >> 4) * 16;
    const uint32_t boff = (uint32_t)((lane >> 4)*8 + (lane & 7)) * PITCHB + (uint32_t)((lane >> 3) & 1) * 16;

    const uint32_t As[3] = { smem_u32(AH), smem_u32(AH), smem_u32(AL) };
    const uint32_t Bs[3] = { smem_u32(CH), smem_u32(CL), smem_u32(CH) };
    #pragma unroll
    for (int s = 0; s < 3; s++) {
        #pragma unroll
        for (int kk = 0; kk < 4; kk++) {
            uint32_t a0, a1, a2, a3;
            ldsm_x4(a0, a1, a2, a3, As[s] + arow + kk*32);
            #pragma unroll
            for (int pp = 0; pp < 8; pp++) {
                uint32_t b0, b1, b2, b3;
                ldsm_x4(b0, b1, b2, b3, Bs[s] + boff + (uint32_t)pp*16*PITCHB + kk*32);
                mma16816(c[2*pp],   a0, a1, a2, a3, b0, b1);
                mma16816(c[2*pp+1], a0, a1, a2, a3, b2, b3);
            }
        }
    }

    const int qr = lane >> 2;
    const int qc = lane & 3;
    #pragma unroll
    for (int nt = 0; nt < 16; nt++) {
        int hi = nt >> 3;
        int oc = (nt & 7)*8 + qc*2;
        float* d0 = out + ((size_t)b << 22) + ((size_t)oc << 16) + (size_t)hi*NV + n0 + m0 + qr;
        d0[0] = c[nt][0];
        d0[1 << 16] = c[nt][1];
        d0[8] = c[nt][2];
        d0[(1 << 16) + 8] = c[nt][3];
    }
}

// ---------------- launch ----------------
extern "C" void kernel_launch(void* const* d_in, const int* in_sizes, int n_in,
                              void* d_out, int out_size) {
    const float* x  = (const float*)d_in[0];
    const float* wp = (const float*)d_in[1];
    const float* wt = (const float*)d_in[2];
    const float* wg = (const float*)d_in[3];
    const float* wm = (const float*)d_in[4];
    float* out = (float*)d_out;

    static bool attr_done = false;
    if (!attr_done) {
        cudaFuncSetAttribute(k_fused, cudaFuncAttributeMaxDynamicSharedMemorySize, SMEM_FUSED);
        cudaFuncSetAttribute(k_out,   cudaFuncAttributeMaxDynamicSharedMemorySize, SMEM_OUT);
        attr_done = true;
    }

    k_init <<<128, 256>>>();
    k_fused<<<B * (NV/256), 256, SMEM_FUSED>>>(x, wp, wt, wg);
    k_cmat <<<128, 256>>>(wm);
    k_out  <<<B * (NV/64), 128, SMEM_OUT>>>(out);
}

// round 16
// speedup vs baseline: 1.3084x; 1.3084x over previous
#include <cuda_runtime.h>
#include <cuda_fp16.h>
#include <cstdint>

#define B   8
#define C   64
#define IC  32
#define HW  65536
#define NV  32768
#define TOT (IC*HW)

// C power-of-2 prescale (k_cmat multiplies, k_out divides)
#define C_SCALE    1073741824.0f          // 2^30
#define C_UNSCALE  9.313225746154785e-10f // 2^-30

// ---------------- scratch ----------------
__device__ float s_theta[(size_t)B*TOT];
__device__ float s_att[B*64*64];
__device__ float s_sum[2*B];               // [0..7]=Sphi, [8..15]=Sg
__device__ uint32_t s_CH[8*128*36];        // C*2^30 fp16-hi image, row=hi*64+o, pitch 36 words
__device__ uint32_t s_CL[8*128*36];        // C*2^30 fp16-lo image

// ---------------- helpers ----------------
__device__ __forceinline__ uint32_t smem_u32(const void* p) {
    uint32_t a;
    asm("{ .reg .u64 t; cvta.to.shared.u64 t, %1; cvt.u32.u64 %0, t; }" : "=r"(a) : "l"(p));
    return a;
}
__device__ __forceinline__ void ldsm_x4(uint32_t& r0, uint32_t& r1, uint32_t& r2, uint32_t& r3, uint32_t addr) {
    asm volatile("ldmatrix.sync.aligned.m8n8.x4.shared.b16 {%0,%1,%2,%3}, [%4];"
                 : "=r"(r0), "=r"(r1), "=r"(r2), "=r"(r3) : "r"(addr));
}
// fp16 HMMA m16n8k16, fp32 accum
__device__ __forceinline__ void mma16816(float* c, uint32_t a0, uint32_t a1, uint32_t a2, uint32_t a3,
                                         uint32_t b0, uint32_t b1) {
    asm volatile("mma.sync.aligned.m16n8k16.row.col.f32.f16.f16.f32 "
                 "{%0,%1,%2,%3}, {%4,%5,%6,%7}, {%8,%9}, {%0,%1,%2,%3};"
                 : "+f"(c[0]), "+f"(c[1]), "+f"(c[2]), "+f"(c[3])
                 : "r"(a0), "r"(a1), "r"(a2), "r"(a3), "r"(b0), "r"(b1));
}
// pack two floats to fp16x2 (hi only)
__device__ __forceinline__ uint32_t pack_h(float v0, float v1) {
    __half h0 = __float2half_rn(v0), h1 = __float2half_rn(v1);
    return (uint32_t)__half_as_ushort(h0) | ((uint32_t)__half_as_ushort(h1) << 16);
}
// fp16 hi/lo split of a pair of floats
__device__ __forceinline__ void split_pair_h(float v0, float v1, uint32_t& hpk, uint32_t& lpk) {
    __half h0 = __float2half_rn(v0), h1 = __float2half_rn(v1);
    hpk = (uint32_t)__half_as_ushort(h0) | ((uint32_t)__half_as_ushort(h1) << 16);
    float l0 = v0 - __half2float(h0), l1 = v1 - __half2float(h1);
    __half g0 = __float2half_rn(l0), g1 = __float2half_rn(l1);
    lpk = (uint32_t)__half_as_ushort(g0) | ((uint32_t)__half_as_ushort(g1) << 16);
}

#define PITCH  72
#define PITCHB 144

// smem offsets for k_fused (bytes): AH 128 rows, WH 96, WL 32 (theta only), EG 64, EP 64
#define OFF_AH 0
#define OFF_WH (128*PITCHB)
#define OFF_WL (128*PITCHB + 96*PITCHB)
#define OFF_EG (128*PITCHB + 96*PITCHB + 32*PITCHB)
#define OFF_EP (OFF_EG + 64*PITCHB)
#define SMEM_FUSED (OFF_EP + 64*PITCHB)     // 55296 B

// smem for k_out: AH 128, CH 128, CL 128
#define O_AH 0
#define O_CH (128*PITCHB)
#define O_CL (2*128*PITCHB)
#define SMEM_OUT (3*128*PITCHB)             // 55296 B

// ---------------- K0: reset accumulators ----------------
__global__ void k_init() {
    int i = blockIdx.x * 256 + threadIdx.x;
    if (i < B*4096) s_att[i] = 0.0f;
    if (i < 2*B) s_sum[i] = 0.0f;
}

// ---------------- K1: fused conv + exp + att-partial + theta store (fp16 basis) ----------------
// Conv: phi/g = single product (xh*wh); theta = xh*wh + xh*wl (w full, x-lo dropped).
__global__ __launch_bounds__(256) void k_fused(const float* __restrict__ x,
                                               const float* __restrict__ wp,
                                               const float* __restrict__ wt,
                                               const float* __restrict__ wg) {
    extern __shared__ char dsm[];
    char* AH = dsm + OFF_AH;
    char* WH = dsm + OFF_WH;
    char* WL = dsm + OFF_WL;
    char* EG = dsm + OFF_EG;
    char* EP = dsm + OFF_EP;
    __shared__ float rsp[8], rsg[8];

    const int tid  = threadIdx.x;
    const int lane = tid & 31;
    const int wid  = tid >> 5;
    const int b    = blockIdx.x >> 7;
    const int v0   = (blockIdx.x & 127) << 8;

    // weights -> smem: rows 0-31 phi, 32-63 g, 64-95 theta; WL holds theta-lo (rows 0-31 compact)
    for (int i = tid; i < 96*32; i += 256) {
        int row = i >> 5, pr = i & 31;
        const float* src = (row < 32) ? (wp + row*64)
                          : (row < 64 ? wg + (row-32)*64 : wt + (row-64)*64);
        uint32_t h, l;
        split_pair_h(src[pr*2], src[pr*2+1], h, l);
        *(uint32_t*)(WH + row*PITCHB + pr*4) = h;
        if (row >= 64)
            *(uint32_t*)(WL + (row-64)*PITCHB + pr*4) = l;
    }

    const int mt = wid & 3;
    const int ng = wid >> 2;
    float attc[4][4];
    #pragma unroll
    for (int j = 0; j < 4; j++)
        #pragma unroll
        for (int q = 0; q < 4; q++) attc[j][q] = 0.0f;
    float sp = 0.0f, sg = 0.0f;

    const uint32_t arow  = (uint32_t)(wid*16 + (lane & 15)) * PITCHB + (uint32_t)(lane >> 4) * 16;
    const uint32_t boff  = (uint32_t)((lane >> 4)*8 + (lane & 7)) * PITCHB + (uint32_t)((lane >> 3) & 1) * 16;
    const uint32_t arow2 = (uint32_t)(mt*16 + (lane & 15)) * PITCHB + (uint32_t)(lane >> 4) * 16;
    const int qr = lane >> 2;
    const int qc = lane & 3;

    const uint32_t ahb = smem_u32(AH);
    const uint32_t whb = smem_u32(WH), wlb = smem_u32(WL);
    const uint32_t egb = smem_u32(EG), epb = smem_u32(EP);
    __syncthreads();

    for (int it = 0; it < 4; it++) {
        const int n0it = v0 + it*64;
        // ---- stage x tile (hi only): px 0-63 = half0, 64-127 = half1 ----
        {
            const int px = tid & 127;
            const int hi = px >> 6;
            const int j0 = (tid >> 7) * 16;
            const float* xb = x + ((size_t)b << 22) + (size_t)hi*NV + n0it + (px & 63);
            #pragma unroll
            for (int j = j0; j < j0 + 16; j++) {
                float v0f = xb[(size_t)(2*j)   << 16];
                float v1f = xb[(size_t)(2*j+1) << 16];
                *(uint32_t*)(AH + px*PITCHB + j*4) = pack_h(v0f, v1f);
            }
        }
        __syncthreads();

        // ---- conv mma: single product phi/g (pp 0..3); + w-lo for theta (pp 4,5) ----
        float c[12][4];
        #pragma unroll
        for (int nt = 0; nt < 12; nt++)
            #pragma unroll
            for (int q = 0; q < 4; q++) c[nt][q] = 0.0f;

        #pragma unroll
        for (int kk = 0; kk < 4; kk++) {
            uint32_t ah0, ah1, ah2, ah3;
            ldsm_x4(ah0, ah1, ah2, ah3, ahb + arow + kk*32);
            #pragma unroll
            for (int pp = 0; pp < 6; pp++) {
                uint32_t bh0, bh1, bh2, bh3;
                ldsm_x4(bh0, bh1, bh2, bh3, whb + boff + (uint32_t)pp*16*PITCHB + kk*32);
                mma16816(c[2*pp],   ah0, ah1, ah2, ah3, bh0, bh1);
                mma16816(c[2*pp+1], ah0, ah1, ah2, ah3, bh2, bh3);
                if (pp >= 4) {
                    uint32_t bl0, bl1, bl2, bl3;
                    ldsm_x4(bl0, bl1, bl2, bl3, wlb + boff + (uint32_t)(pp-4)*16*PITCHB + kk*32);
                    mma16816(c[2*pp],   ah0, ah1, ah2, ah3, bl0, bl1);
                    mma16816(c[2*pp+1], ah0, ah1, ah2, ah3, bl2, bl3);
                }
            }
        }

        // ---- epilogue: theta -> gmem fp32, exp(phi/g) -> smem fp16 ----
        const int r1 = wid*16 + qr;
        const int hi1 = r1 >> 6;
        const int nl1 = r1 & 63;
        #pragma unroll
        for (int nt = 0; nt < 12; nt++) {
            const int oc = nt*8 + qc*2;
            const int t  = oc >> 5;
            const int ocl = oc & 31;
            if (t == 2) {
                float* d0 = s_theta + (size_t)b*TOT + ((size_t)ocl << 16)
                          + (size_t)hi1*NV + n0it + nl1;
                d0[0] = c[nt][0];
                d0[1 << 16] = c[nt][1];
                d0[8] = c[nt][2];
                d0[(1 << 16) + 8] = c[nt][3];
            } else {
                char* base = (t == 1) ? EG : EP;
                float e0 = __expf(c[nt][0]);
                float e1 = __expf(c[nt][1]);
                float e2 = __expf(c[nt][2]);
                float e3 = __expf(c[nt][3]);
                *(__half*)(base + (2*ocl + hi1)*PITCHB + nl1*2)         = __float2half_rn(e0);
                *(__half*)(base + (2*ocl + 2 + hi1)*PITCHB + nl1*2)     = __float2half_rn(e1);
                *(__half*)(base + (2*ocl + hi1)*PITCHB + (nl1+8)*2)     = __float2half_rn(e2);
                *(__half*)(base + (2*ocl + 2 + hi1)*PITCHB + (nl1+8)*2) = __float2half_rn(e3);
                float s4 = (e0 + e1) + (e2 + e3);
                if (t == 0) sp += s4; else sg += s4;
            }
        }
        __syncthreads();

        // ---- att mma: attc += EG(m) @ EP(n)^T over k=64 local cols ----
        #pragma unroll
        for (int kk = 0; kk < 4; kk++) {
            uint32_t a0, a1, a2, a3;
            ldsm_x4(a0, a1, a2, a3, egb + arow2 + kk*32);
            #pragma unroll
            for (int p = 0; p < 2; p++) {
                uint32_t b0, b1, b2, b3;
                ldsm_x4(b0, b1, b2, b3, epb + boff + (uint32_t)(ng*4 + 2*p)*8*PITCHB + kk*32);
                mma16816(attc[2*p],   a0, a1, a2, a3, b0, b1);
                mma16816(attc[2*p+1], a0, a1, a2, a3, b2, b3);
            }
        }
        __syncthreads();
    }

    float* attb = s_att + b*4096;
    #pragma unroll
    for (int j = 0; j < 4; j++) {
        const int col = (ng*4 + j)*8 + qc*2;
        const int row = mt*16 + qr;
        atomicAdd(&attb[row*64 + col],           attc[j][0]);
        atomicAdd(&attb[row*64 + col + 1],       attc[j][1]);
        atomicAdd(&attb[(row + 8)*64 + col],     attc[j][2]);
        atomicAdd(&attb[(row + 8)*64 + col + 1], attc[j][3]);
    }

    #pragma unroll
    for (int off = 16; off; off >>= 1) {
        sp += __shfl_xor_sync(0xffffffffu, sp, off);
        sg += __shfl_xor_sync(0xffffffffu, sg, off);
    }
    if (lane == 0) { rsp[wid] = sp; rsg[wid] = sg; }
    __syncthreads();
    if (tid == 0) {
        float a = 0.0f, bm = 0.0f;
        #pragma unroll
        for (int i = 0; i < 8; i++) { a += rsp[i]; bm += rsg[i]; }
        atomicAdd(&s_sum[b],     a);
        atomicAdd(&s_sum[B + b], bm);
    }
}

// ---------------- K2: fold mask + norm into scaled fp16 hi/lo C image ----------------
__global__ void k_cmat(const float* __restrict__ wm) {
    int idx = blockIdx.x * 256 + threadIdx.x;    // 32768
    int dd = idx & 31;
    int o  = (idx >> 5) & 63;
    int hi = (idx >> 11) & 1;
    int b  = idx >> 12;
    float inv = C_SCALE / (s_sum[b] * s_sum[B + b]);
    const float* attb = s_att + b*4096;
    float a0 = 0.0f, a1 = 0.0f;
    #pragma unroll
    for (int i = 0; i < 32; i++) {
        float w = wm[o*32 + i];
        a0 += w * attb[(2*i + hi)*64 + 2*dd];
        a1 += w * attb[(2*i + hi)*64 + 2*dd + 1];
    }
    uint32_t h, l;
    split_pair_h(a0 * inv, a1 * inv, h, l);
    int word = b*4608 + (hi*64 + o)*36 + dd;
    s_CH[word] = h;
    s_CL[word] = l;
}

// ---------------- K3: Out = C @ theta, fp16, theta-hi only, Ch+Cl products ----------------
__global__ __launch_bounds__(256) void k_out(float* __restrict__ out) {
    extern __shared__ char dsm[];
    char* AH = dsm + O_AH;
    char* CH = dsm + O_CH;
    char* CL = dsm + O_CL;

    const int tid  = threadIdx.x;
    const int lane = tid & 31;
    const int wid  = tid >> 5;
    const int b    = blockIdx.x >> 8;
    const int n0   = (blockIdx.x & 255) << 7;

    // stage C image: plain vector copy (pre-split in k_cmat)
    {
        const uint4* srcH = (const uint4*)(s_CH + b*4608);
        const uint4* srcL = (const uint4*)(s_CL + b*4608);
        uint4* dstH = (uint4*)CH;
        uint4* dstL = (uint4*)CL;
        #pragma unroll
        for (int i = 0; i < 5; i++) {
            int k = tid + i*256;
            if (k < 1152) { dstH[k] = srcH[k]; dstL[k] = srcL[k]; }
        }
    }
    // stage theta (hi only): A[n][d], d=2j,2j+1 from raw[j][(d&1)*NV + n]
    {
        const int px = tid & 127;
        const int j0 = (tid >> 7) * 16;
        const float* th = s_theta + (size_t)b*TOT + n0 + px;
        #pragma unroll
        for (int j = j0; j < j0 + 16; j++) {
            float v0 = th[(size_t)j << 16];
            float v1 = th[((size_t)j << 16) + NV];
            *(uint32_t*)(AH + px*PITCHB + j*4) = pack_h(v0, v1);
        }
    }
    __syncthreads();

    const int m0 = wid * 16;
    float c[16][4];
    #pragma unroll
    for (int nt = 0; nt < 16; nt++)
        #pragma unroll
        for (int q = 0; q < 4; q++) c[nt][q] = 0.0f;

    const uint32_t arow = (uint32_t)(m0 + (lane & 15)) * PITCHB + (uint32_t)(lane >> 4) * 16;
    const uint32_t boff = (uint32_t)((lane >> 4)*8 + (lane & 7)) * PITCHB + (uint32_t)((lane >> 3) & 1) * 16;
    const uint32_t ahb = smem_u32(AH);
    const uint32_t chb = smem_u32(CH), clb = smem_u32(CL);

    #pragma unroll
    for (int kk = 0; kk < 4; kk++) {
        uint32_t a0, a1, a2, a3;
        ldsm_x4(a0, a1, a2, a3, ahb + arow + kk*32);
        #pragma unroll
        for (int pp = 0; pp < 8; pp++) {
            uint32_t bh0, bh1, bh2, bh3;
            ldsm_x4(bh0, bh1, bh2, bh3, chb + boff + (uint32_t)pp*16*PITCHB + kk*32);
            mma16816(c[2*pp],   a0, a1, a2, a3, bh0, bh1);
            mma16816(c[2*pp+1], a0, a1, a2, a3, bh2, bh3);
            uint32_t bl0, bl1, bl2, bl3;
            ldsm_x4(bl0, bl1, bl2, bl3, clb + boff + (uint32_t)pp*16*PITCHB + kk*32);
            mma16816(c[2*pp],   a0, a1, a2, a3, bl0, bl1);
            mma16816(c[2*pp+1], a0, a1, a2, a3, bl2, bl3);
        }
    }

    const int qr = lane >> 2;
    const int qc = lane & 3;
    #pragma unroll
    for (int nt = 0; nt < 16; nt++) {
        int hi = nt >> 3;
        int oc = (nt & 7)*8 + qc*2;
        float* d0 = out + ((size_t)b << 22) + ((size_t)oc << 16) + (size_t)hi*NV + n0 + m0 + qr;
        d0[0] = c[nt][0] * C_UNSCALE;
        d0[1 << 16] = c[nt][1] * C_UNSCALE;
        d0[8] = c[nt][2] * C_UNSCALE;
        d0[(1 << 16) + 8] = c[nt][3] * C_UNSCALE;
    }
}

// ---------------- launch ----------------
extern "C" void kernel_launch(void* const* d_in, const int* in_sizes, int n_in,
                              void* d_out, int out_size) {
    const float* x  = (const float*)d_in[0];
    const float* wp = (const float*)d_in[1];
    const float* wt = (const float*)d_in[2];
    const float* wg = (const float*)d_in[3];
    const float* wm = (const float*)d_in[4];
    float* out = (float*)d_out;

    static bool attr_done = false;
    if (!attr_done) {
        cudaFuncSetAttribute(k_fused, cudaFuncAttributeMaxDynamicSharedMemorySize, SMEM_FUSED);
        cudaFuncSetAttribute(k_out,   cudaFuncAttributeMaxDynamicSharedMemorySize, SMEM_OUT);
        attr_done = true;
    }

    k_init <<<128, 256>>>();
    k_fused<<<B * (NV/256), 256, SMEM_FUSED>>>(x, wp, wt, wg);
    k_cmat <<<128, 256>>>(wm);
    k_out  <<<B * (NV/128), 256, SMEM_OUT>>>(out);
}

// round 17
// speedup vs baseline: 1.3443x; 1.0274x over previous
#include <cuda_runtime.h>
#include <cuda_fp16.h>
#include <cstdint>

#define B   8
#define C   64
#define IC  32
#define HW  65536
#define NV  32768
#define TOT (IC*HW)

// C power-of-2 prescale (k_cmat multiplies, k_out divides)
#define C_SCALE    1073741824.0f          // 2^30
#define C_UNSCALE  9.313225746154785e-10f // 2^-30

// ---------------- scratch ----------------
__device__ float s_theta[(size_t)B*TOT];
__device__ float s_att[B*64*64];
__device__ float s_sum[2*B];               // [0..7]=Sphi, [8..15]=Sg
__device__ uint32_t s_CH[8*128*36];        // C*2^30 fp16-hi image, row=hi*64+o, pitch 36 words
__device__ uint32_t s_CL[8*128*36];        // C*2^30 fp16-lo image

// ---------------- helpers ----------------
__device__ __forceinline__ uint32_t smem_u32(const void* p) {
    uint32_t a;
    asm("{ .reg .u64 t; cvta.to.shared.u64 t, %1; cvt.u32.u64 %0, t; }" : "=r"(a) : "l"(p));
    return a;
}
__device__ __forceinline__ void ldsm_x4(uint32_t& r0, uint32_t& r1, uint32_t& r2, uint32_t& r3, uint32_t addr) {
    asm volatile("ldmatrix.sync.aligned.m8n8.x4.shared.b16 {%0,%1,%2,%3}, [%4];"
                 : "=r"(r0), "=r"(r1), "=r"(r2), "=r"(r3) : "r"(addr));
}
// fp16 HMMA m16n8k16, fp32 accum
__device__ __forceinline__ void mma16816(float* c, uint32_t a0, uint32_t a1, uint32_t a2, uint32_t a3,
                                         uint32_t b0, uint32_t b1) {
    asm volatile("mma.sync.aligned.m16n8k16.row.col.f32.f16.f16.f32 "
                 "{%0,%1,%2,%3}, {%4,%5,%6,%7}, {%8,%9}, {%0,%1,%2,%3};"
                 : "+f"(c[0]), "+f"(c[1]), "+f"(c[2]), "+f"(c[3])
                 : "r"(a0), "r"(a1), "r"(a2), "r"(a3), "r"(b0), "r"(b1));
}
// pack two floats to fp16x2 (hi only)
__device__ __forceinline__ uint32_t pack_h(float v0, float v1) {
    __half h0 = __float2half_rn(v0), h1 = __float2half_rn(v1);
    return (uint32_t)__half_as_ushort(h0) | ((uint32_t)__half_as_ushort(h1) << 16);
}
// fp16 hi/lo split of a pair of floats
__device__ __forceinline__ void split_pair_h(float v0, float v1, uint32_t& hpk, uint32_t& lpk) {
    __half h0 = __float2half_rn(v0), h1 = __float2half_rn(v1);
    hpk = (uint32_t)__half_as_ushort(h0) | ((uint32_t)__half_as_ushort(h1) << 16);
    float l0 = v0 - __half2float(h0), l1 = v1 - __half2float(h1);
    __half g0 = __float2half_rn(l0), g1 = __float2half_rn(l1);
    lpk = (uint32_t)__half_as_ushort(g0) | ((uint32_t)__half_as_ushort(g1) << 16);
}

#define PITCH  72
#define PITCHB 144

// smem offsets for k_fused (bytes): AH 128 rows, WH 96, WL 32 (theta only), EG 64, EP 64
#define OFF_AH 0
#define OFF_WH (128*PITCHB)
#define OFF_WL (128*PITCHB + 96*PITCHB)
#define OFF_EG (128*PITCHB + 96*PITCHB + 32*PITCHB)
#define OFF_EP (OFF_EG + 64*PITCHB)
#define SMEM_FUSED (OFF_EP + 64*PITCHB)     // 55296 B

// smem for k_out: AH 128, CH 128, CL 128
#define O_AH 0
#define O_CH (128*PITCHB)
#define O_CL (2*128*PITCHB)
#define SMEM_OUT (3*128*PITCHB)             // 55296 B

// ---------------- K0: reset accumulators ----------------
__global__ void k_init() {
    int i = blockIdx.x * 256 + threadIdx.x;
    if (i < B*4096) s_att[i] = 0.0f;
    if (i < 2*B) s_sum[i] = 0.0f;
}

// ---------------- K1: fused conv + exp + att-partial + theta store (fp16 basis, R16 form) ----------------
__global__ __launch_bounds__(256) void k_fused(const float* __restrict__ x,
                                               const float* __restrict__ wp,
                                               const float* __restrict__ wt,
                                               const float* __restrict__ wg) {
    extern __shared__ char dsm[];
    char* AH = dsm + OFF_AH;
    char* WH = dsm + OFF_WH;
    char* WL = dsm + OFF_WL;
    char* EG = dsm + OFF_EG;
    char* EP = dsm + OFF_EP;
    __shared__ float rsp[8], rsg[8];

    const int tid  = threadIdx.x;
    const int lane = tid & 31;
    const int wid  = tid >> 5;
    const int b    = blockIdx.x >> 7;
    const int v0   = (blockIdx.x & 127) << 8;

    // weights -> smem: rows 0-31 phi, 32-63 g, 64-95 theta; WL holds theta-lo (rows 0-31 compact)
    for (int i = tid; i < 96*32; i += 256) {
        int row = i >> 5, pr = i & 31;
        const float* src = (row < 32) ? (wp + row*64)
                          : (row < 64 ? wg + (row-32)*64 : wt + (row-64)*64);
        uint32_t h, l;
        split_pair_h(src[pr*2], src[pr*2+1], h, l);
        *(uint32_t*)(WH + row*PITCHB + pr*4) = h;
        if (row >= 64)
            *(uint32_t*)(WL + (row-64)*PITCHB + pr*4) = l;
    }

    const int mt = wid & 3;
    const int ng = wid >> 2;
    float attc[4][4];
    #pragma unroll
    for (int j = 0; j < 4; j++)
        #pragma unroll
        for (int q = 0; q < 4; q++) attc[j][q] = 0.0f;
    float sp = 0.0f, sg = 0.0f;

    const uint32_t arow  = (uint32_t)(wid*16 + (lane & 15)) * PITCHB + (uint32_t)(lane >> 4) * 16;
    const uint32_t boff  = (uint32_t)((lane >> 4)*8 + (lane & 7)) * PITCHB + (uint32_t)((lane >> 3) & 1) * 16;
    const uint32_t arow2 = (uint32_t)(mt*16 + (lane & 15)) * PITCHB + (uint32_t)(lane >> 4) * 16;
    const int qr = lane >> 2;
    const int qc = lane & 3;

    const uint32_t ahb = smem_u32(AH);
    const uint32_t whb = smem_u32(WH), wlb = smem_u32(WL);
    const uint32_t egb = smem_u32(EG), epb = smem_u32(EP);
    __syncthreads();

    for (int it = 0; it < 4; it++) {
        const int n0it = v0 + it*64;
        // ---- stage x tile (hi only): px 0-63 = half0, 64-127 = half1 ----
        {
            const int px = tid & 127;
            const int hi = px >> 6;
            const int j0 = (tid >> 7) * 16;
            const float* xb = x + ((size_t)b << 22) + (size_t)hi*NV + n0it + (px & 63);
            #pragma unroll
            for (int j = j0; j < j0 + 16; j++) {
                float v0f = xb[(size_t)(2*j)   << 16];
                float v1f = xb[(size_t)(2*j+1) << 16];
                *(uint32_t*)(AH + px*PITCHB + j*4) = pack_h(v0f, v1f);
            }
        }
        __syncthreads();

        // ---- conv mma: single product phi/g (pp 0..3); + w-lo for theta (pp 4,5) ----
        float c[12][4];
        #pragma unroll
        for (int nt = 0; nt < 12; nt++)
            #pragma unroll
            for (int q = 0; q < 4; q++) c[nt][q] = 0.0f;

        #pragma unroll
        for (int kk = 0; kk < 4; kk++) {
            uint32_t ah0, ah1, ah2, ah3;
            ldsm_x4(ah0, ah1, ah2, ah3, ahb + arow + kk*32);
            #pragma unroll
            for (int pp = 0; pp < 6; pp++) {
                uint32_t bh0, bh1, bh2, bh3;
                ldsm_x4(bh0, bh1, bh2, bh3, whb + boff + (uint32_t)pp*16*PITCHB + kk*32);
                mma16816(c[2*pp],   ah0, ah1, ah2, ah3, bh0, bh1);
                mma16816(c[2*pp+1], ah0, ah1, ah2, ah3, bh2, bh3);
                if (pp >= 4) {
                    uint32_t bl0, bl1, bl2, bl3;
                    ldsm_x4(bl0, bl1, bl2, bl3, wlb + boff + (uint32_t)(pp-4)*16*PITCHB + kk*32);
                    mma16816(c[2*pp],   ah0, ah1, ah2, ah3, bl0, bl1);
                    mma16816(c[2*pp+1], ah0, ah1, ah2, ah3, bl2, bl3);
                }
            }
        }

        // ---- epilogue: theta -> gmem fp32, exp(phi/g) -> smem fp16 ----
        const int r1 = wid*16 + qr;
        const int hi1 = r1 >> 6;
        const int nl1 = r1 & 63;
        #pragma unroll
        for (int nt = 0; nt < 12; nt++) {
            const int oc = nt*8 + qc*2;
            const int t  = oc >> 5;
            const int ocl = oc & 31;
            if (t == 2) {
                float* d0 = s_theta + (size_t)b*TOT + ((size_t)ocl << 16)
                          + (size_t)hi1*NV + n0it + nl1;
                d0[0] = c[nt][0];
                d0[1 << 16] = c[nt][1];
                d0[8] = c[nt][2];
                d0[(1 << 16) + 8] = c[nt][3];
            } else {
                char* base = (t == 1) ? EG : EP;
                float e0 = __expf(c[nt][0]);
                float e1 = __expf(c[nt][1]);
                float e2 = __expf(c[nt][2]);
                float e3 = __expf(c[nt][3]);
                *(__half*)(base + (2*ocl + hi1)*PITCHB + nl1*2)         = __float2half_rn(e0);
                *(__half*)(base + (2*ocl + 2 + hi1)*PITCHB + nl1*2)     = __float2half_rn(e1);
                *(__half*)(base + (2*ocl + hi1)*PITCHB + (nl1+8)*2)     = __float2half_rn(e2);
                *(__half*)(base + (2*ocl + 2 + hi1)*PITCHB + (nl1+8)*2) = __float2half_rn(e3);
                float s4 = (e0 + e1) + (e2 + e3);
                if (t == 0) sp += s4; else sg += s4;
            }
        }
        __syncthreads();

        // ---- att mma: attc += EG(m) @ EP(n)^T over k=64 local cols ----
        #pragma unroll
        for (int kk = 0; kk < 4; kk++) {
            uint32_t a0, a1, a2, a3;
            ldsm_x4(a0, a1, a2, a3, egb + arow2 + kk*32);
            #pragma unroll
            for (int p = 0; p < 2; p++) {
                uint32_t b0, b1, b2, b3;
                ldsm_x4(b0, b1, b2, b3, epb + boff + (uint32_t)(ng*4 + 2*p)*8*PITCHB + kk*32);
                mma16816(attc[2*p],   a0, a1, a2, a3, b0, b1);
                mma16816(attc[2*p+1], a0, a1, a2, a3, b2, b3);
            }
        }
        __syncthreads();
    }

    float* attb = s_att + b*4096;
    #pragma unroll
    for (int j = 0; j < 4; j++) {
        const int col = (ng*4 + j)*8 + qc*2;
        const int row = mt*16 + qr;
        atomicAdd(&attb[row*64 + col],           attc[j][0]);
        atomicAdd(&attb[row*64 + col + 1],       attc[j][1]);
        atomicAdd(&attb[(row + 8)*64 + col],     attc[j][2]);
        atomicAdd(&attb[(row + 8)*64 + col + 1], attc[j][3]);
    }

    #pragma unroll
    for (int off = 16; off; off >>= 1) {
        sp += __shfl_xor_sync(0xffffffffu, sp, off);
        sg += __shfl_xor_sync(0xffffffffu, sg, off);
    }
    if (lane == 0) { rsp[wid] = sp; rsg[wid] = sg; }
    __syncthreads();
    if (tid == 0) {
        float a = 0.0f, bm = 0.0f;
        #pragma unroll
        for (int i = 0; i < 8; i++) { a += rsp[i]; bm += rsg[i]; }
        atomicAdd(&s_sum[b],     a);
        atomicAdd(&s_sum[B + b], bm);
    }
}

// ---------------- K2: fold mask + norm into scaled fp16 hi/lo C image ----------------
__global__ void k_cmat(const float* __restrict__ wm) {
    int idx = blockIdx.x * 256 + threadIdx.x;    // 32768
    int dd = idx & 31;
    int o  = (idx >> 5) & 63;
    int hi = (idx >> 11) & 1;
    int b  = idx >> 12;
    float inv = C_SCALE / (s_sum[b] * s_sum[B + b]);
    const float* attb = s_att + b*4096;
    float a0 = 0.0f, a1 = 0.0f;
    #pragma unroll
    for (int i = 0; i < 32; i++) {
        float w = wm[o*32 + i];
        a0 += w * attb[(2*i + hi)*64 + 2*dd];
        a1 += w * attb[(2*i + hi)*64 + 2*dd + 1];
    }
    uint32_t h, l;
    split_pair_h(a0 * inv, a1 * inv, h, l);
    int word = b*4608 + (hi*64 + o)*36 + dd;
    s_CH[word] = h;
    s_CL[word] = l;
}

// ---------------- K3: Out = C @ theta, operand-swapped: C = A (per-warp m16), theta = B ----------------
// Two 64-px halves; Ch/Cl fragments loaded once per kk and shared across all theta n-tiles.
__global__ __launch_bounds__(256) void k_out(float* __restrict__ out) {
    extern __shared__ char dsm[];
    char* AH = dsm + O_AH;
    char* CH = dsm + O_CH;
    char* CL = dsm + O_CL;

    const int tid  = threadIdx.x;
    const int lane = tid & 31;
    const int wid  = tid >> 5;
    const int b    = blockIdx.x >> 8;
    const int n0   = (blockIdx.x & 255) << 7;

    // stage C image: plain vector copy (pre-split in k_cmat)
    {
        const uint4* srcH = (const uint4*)(s_CH + b*4608);
        const uint4* srcL = (const uint4*)(s_CL + b*4608);
        uint4* dstH = (uint4*)CH;
        uint4* dstL = (uint4*)CL;
        #pragma unroll
        for (int i = 0; i < 5; i++) {
            int k = tid + i*256;
            if (k < 1152) { dstH[k] = srcH[k]; dstL[k] = srcL[k]; }
        }
    }
    // stage theta (hi only): AH[px][d], d=2j,2j+1 from raw[j][(d&1)*NV + n]
    {
        const int px = tid & 127;
        const int j0 = (tid >> 7) * 16;
        const float* th = s_theta + (size_t)b*TOT + n0 + px;
        #pragma unroll
        for (int j = j0; j < j0 + 16; j++) {
            float v0 = th[(size_t)j << 16];
            float v1 = th[((size_t)j << 16) + NV];
            *(uint32_t*)(AH + px*PITCHB + j*4) = pack_h(v0, v1);
        }
    }
    __syncthreads();

    // A-operand = C rows (warp owns rows wid*16 .. +15); B-operand = theta px
    const uint32_t arow = (uint32_t)(wid*16 + (lane & 15)) * PITCHB + (uint32_t)(lane >> 4) * 16;
    const uint32_t boff = (uint32_t)((lane >> 4)*8 + (lane & 7)) * PITCHB + (uint32_t)((lane >> 3) & 1) * 16;
    const uint32_t ahb = smem_u32(AH);
    const uint32_t chb = smem_u32(CH), clb = smem_u32(CL);

    const int qr = lane >> 2;
    const int qc = lane & 3;
    const int crow0 = wid*16 + qr;
    const int crow1 = crow0 + 8;
    const int hi0 = crow0 >> 6, oc0 = crow0 & 63;
    const int hi1 = crow1 >> 6, oc1 = crow1 & 63;
    float* ob0 = out + ((size_t)b << 22) + ((size_t)oc0 << 16) + (size_t)hi0*NV + n0;
    float* ob1 = out + ((size_t)b << 22) + ((size_t)oc1 << 16) + (size_t)hi1*NV + n0;

    #pragma unroll
    for (int h = 0; h < 2; h++) {
        float c[8][4];
        #pragma unroll
        for (int nt = 0; nt < 8; nt++)
            #pragma unroll
            for (int q = 0; q < 4; q++) c[nt][q] = 0.0f;

        #pragma unroll
        for (int kk = 0; kk < 4; kk++) {
            uint32_t ah0, ah1, ah2, ah3, al0, al1, al2, al3;
            ldsm_x4(ah0, ah1, ah2, ah3, chb + arow + kk*32);
            ldsm_x4(al0, al1, al2, al3, clb + arow + kk*32);
            #pragma unroll
            for (int p = 0; p < 4; p++) {
                uint32_t b0, b1, b2, b3;
                ldsm_x4(b0, b1, b2, b3,
                        ahb + boff + (uint32_t)(h*64 + p*16)*PITCHB + kk*32);
                mma16816(c[2*p],   ah0, ah1, ah2, ah3, b0, b1);
                mma16816(c[2*p+1], ah0, ah1, ah2, ah3, b2, b3);
                mma16816(c[2*p],   al0, al1, al2, al3, b0, b1);
                mma16816(c[2*p+1], al0, al1, al2, al3, b2, b3);
            }
        }

        // epilogue: c[nt] covers px = h*64 + nt*8 + qc*2 (+1), rows crow0/crow1
        #pragma unroll
        for (int nt = 0; nt < 8; nt++) {
            const int px = h*64 + nt*8 + qc*2;
            *(float2*)(ob0 + px) = make_float2(c[nt][0] * C_UNSCALE, c[nt][1] * C_UNSCALE);
            *(float2*)(ob1 + px) = make_float2(c[nt][2] * C_UNSCALE, c[nt][3] * C_UNSCALE);
        }
    }
}

// ---------------- launch ----------------
extern "C" void kernel_launch(void* const* d_in, const int* in_sizes, int n_in,
                              void* d_out, int out_size) {
    const float* x  = (const float*)d_in[0];
    const float* wp = (const float*)d_in[1];
    const float* wt = (const float*)d_in[2];
    const float* wg = (const float*)d_in[3];
    const float* wm = (const float*)d_in[4];
    float* out = (float*)d_out;

    static bool attr_done = false;
    if (!attr_done) {
        cudaFuncSetAttribute(k_fused, cudaFuncAttributeMaxDynamicSharedMemorySize, SMEM_FUSED);
        cudaFuncSetAttribute(k_out,   cudaFuncAttributeMaxDynamicSharedMemorySize, SMEM_OUT);
        attr_done = true;
    }

    k_init <<<128, 256>>>();
    k_fused<<<B * (NV/256), 256, SMEM_FUSED>>>(x, wp, wt, wg);
    k_cmat <<<128, 256>>>(wm);
    k_out  <<<B * (NV/128), 256, SMEM_OUT>>>(out);
}